// round 1
// baseline (speedup 1.0000x reference)
#include <cuda_runtime.h>

#define IMG_H 512
#define IMG_W 512
#define TILE_W 128
#define TILE_H 16
#define SMEM_W 130           // TILE_W + 2 halo
#define SMEM_H 18            // TILE_H + 2 halo
#define SMEM_STRIDE 132      // padded so row*stride*4B is 16B-aligned (132*4=528, 528%16==0)

__device__ __forceinline__ void s2(float& a, float& b) {
    float t = fminf(a, b);
    b = fmaxf(a, b);
    a = t;
}

__device__ __forceinline__ float med3(float a, float b, float c) {
    // median of 3 = max(min(a,b), min(max(a,b), c))
    return fmaxf(fminf(a, b), fminf(fmaxf(a, b), c));
}

__global__ __launch_bounds__(256, 2)
void MedianFilter2D_68745246540291_kernel(const float* __restrict__ in,
                                          float* __restrict__ out) {
    __shared__ float tile[SMEM_H][SMEM_STRIDE];

    const int tx = threadIdx.x;          // 0..31
    const int ty = threadIdx.y;          // 0..7
    const int tid = ty * 32 + tx;

    const int plane = blockIdx.z;        // b*C + c, 48 planes
    const float* __restrict__ ip = in + (size_t)plane * (IMG_H * IMG_W);
    float* __restrict__ op = out + (size_t)plane * (IMG_H * IMG_W);

    const int bx = blockIdx.x * TILE_W;
    const int by = blockIdx.y * TILE_H;

    // ---- Load (TILE+halo) into smem with reflect padding ----
    #pragma unroll
    for (int i = tid; i < SMEM_W * SMEM_H; i += 256) {
        int sy = i / SMEM_W;
        int sx = i - sy * SMEM_W;
        int gy = by + sy - 1;
        int gx = bx + sx - 1;
        gy = (gy < 0) ? -gy : ((gy >= IMG_H) ? 2 * IMG_H - 2 - gy : gy);
        gx = (gx < 0) ? -gx : ((gx >= IMG_W) ? 2 * IMG_W - 2 - gx : gx);
        tile[sy][sx] = ip[gy * IMG_W + gx];
    }
    __syncthreads();

    // Each thread: 4 consecutive output columns (x0..x0+3), 2 output rows.
    const int x0 = tx * 4;               // smem col of leftmost needed column

    #pragma unroll
    for (int rr = 0; rr < 2; rr++) {
        const int oy = ty * 2 + rr;      // output row within tile (0..15)

        // Read 3 smem rows x 6 cols (float4 + float2, both properly aligned)
        float4 a0 = *(const float4*)&tile[oy + 0][x0];
        float2 b0 = *(const float2*)&tile[oy + 0][x0 + 4];
        float4 a1 = *(const float4*)&tile[oy + 1][x0];
        float2 b1 = *(const float2*)&tile[oy + 1][x0 + 4];
        float4 a2 = *(const float4*)&tile[oy + 2][x0];
        float2 b2 = *(const float2*)&tile[oy + 2][x0 + 4];

        // 6 vertical triples (columns), each sorted ascending: lo/mi/hi
        float lo[6], mi[6], hi[6];
        lo[0] = a0.x; mi[0] = a1.x; hi[0] = a2.x;
        lo[1] = a0.y; mi[1] = a1.y; hi[1] = a2.y;
        lo[2] = a0.z; mi[2] = a1.z; hi[2] = a2.z;
        lo[3] = a0.w; mi[3] = a1.w; hi[3] = a2.w;
        lo[4] = b0.x; mi[4] = b1.x; hi[4] = b2.x;
        lo[5] = b0.y; mi[5] = b1.y; hi[5] = b2.y;

        #pragma unroll
        for (int j = 0; j < 6; j++) {
            s2(lo[j], mi[j]);
            s2(mi[j], hi[j]);
            s2(lo[j], mi[j]);
        }

        // Exact 3x3 median from 3 sorted columns:
        //   med3( max(lo_l, lo_c, lo_r), med3(mi_l, mi_c, mi_r), min(hi_l, hi_c, hi_r) )
        float4 res;
        {
            float mx0 = fmaxf(fmaxf(lo[0], lo[1]), lo[2]);
            float mn0 = fminf(fminf(hi[0], hi[1]), hi[2]);
            float md0 = med3(mi[0], mi[1], mi[2]);
            res.x = med3(mx0, md0, mn0);

            float mx1 = fmaxf(fmaxf(lo[1], lo[2]), lo[3]);
            float mn1 = fminf(fminf(hi[1], hi[2]), hi[3]);
            float md1 = med3(mi[1], mi[2], mi[3]);
            res.y = med3(mx1, md1, mn1);

            float mx2 = fmaxf(fmaxf(lo[2], lo[3]), lo[4]);
            float mn2 = fminf(fminf(hi[2], hi[3]), hi[4]);
            float md2 = med3(mi[2], mi[3], mi[4]);
            res.z = med3(mx2, md2, mn2);

            float mx3 = fmaxf(fmaxf(lo[3], lo[4]), lo[5]);
            float mn3 = fminf(fminf(hi[3], hi[4]), hi[5]);
            float md3v = med3(mi[3], mi[4], mi[5]);
            res.w = med3(mx3, md3v, mn3);
        }

        // Coalesced vector store
        *(float4*)&op[(size_t)(by + oy) * IMG_W + bx + x0] = res;
    }
}

extern "C" void kernel_launch(void* const* d_in, const int* in_sizes, int n_in,
                              void* d_out, int out_size) {
    const float* image = (const float*)d_in[0];
    float* out = (float*)d_out;

    // image: [16, 3, 512, 512] -> 48 planes of 512x512
    dim3 block(32, 8, 1);
    dim3 grid(IMG_W / TILE_W, IMG_H / TILE_H, 48);
    MedianFilter2D_68745246540291_kernel<<<grid, block>>>(image, out);
}

// round 2
// speedup vs baseline: 2.1297x; 2.1297x over previous
#include <cuda_runtime.h>

#define IMG_W 512
#define IMG_H 512
#define RPT   16      // output rows per thread
#define FULLMASK 0xffffffffu

__device__ __forceinline__ float med3f(float a, float b, float c) {
    // median of 3 = max(min(a,b), min(max(a,b), c))
    return fmaxf(fminf(a, b), fminf(fmaxf(a, b), c));
}

__device__ __forceinline__ int reflecty(int y) {
    y = (y < 0) ? -y : y;
    return (y >= IMG_H) ? 2 * IMG_H - 2 - y : y;
}

struct SortedRow {
    float lo0, lo1, lo2, lo3;
    float mi0, mi1, mi2, mi3;
    float hi0, hi1, hi2, hi3;
};

// Load one input row (6 needed columns: x0-1 .. x0+4) and produce the
// horizontal sorted triples for the thread's 4 output columns.
__device__ __forceinline__ SortedRow load_sort_row(const float* __restrict__ ip,
                                                   int y, int x0, int lane) {
    y = reflecty(y);
    const float* __restrict__ rp = ip + y * IMG_W;
    float4 v = *(const float4*)(rp + x0);

    // halo columns from neighbor lanes (warp spans 128 contiguous columns)
    float l = __shfl_up_sync(FULLMASK, v.w, 1);
    float r = __shfl_down_sync(FULLMASK, v.x, 1);
    if (lane == 0)  l = rp[(x0 == 0) ? 1 : (x0 - 1)];
    if (lane == 31) r = rp[(x0 + 4 >= IMG_W) ? (IMG_W - 2) : (x0 + 4)];

    float s0 = l, s1 = v.x, s2 = v.y, s3 = v.z, s4 = v.w, s5 = r;

    SortedRow o;
    #define SORT3(a_, b_, c_, LO, MI, HI) {            \
        float a = (a_), b = (b_), c = (c_), t;          \
        t = fminf(a, b); b = fmaxf(a, b); a = t;        \
        t = fminf(b, c); c = fmaxf(b, c); b = t;        \
        t = fminf(a, b); b = fmaxf(a, b); a = t;        \
        o.LO = a; o.MI = b; o.HI = c; }
    SORT3(s0, s1, s2, lo0, mi0, hi0);
    SORT3(s1, s2, s3, lo1, mi1, hi1);
    SORT3(s2, s3, s4, lo2, mi2, hi2);
    SORT3(s3, s4, s5, lo3, mi3, hi3);
    #undef SORT3
    return o;
}

__device__ __forceinline__ float tail(float lA, float lB, float lC,
                                      float mA, float mB, float mC,
                                      float hA, float hB, float hC) {
    float mx = fmaxf(fmaxf(lA, lB), lC);   // max of the three mins
    float mn = fminf(fminf(hA, hB), hC);   // min of the three maxes
    float md = med3f(mA, mB, mC);          // med of the three meds
    return med3f(mx, md, mn);
}

__global__ __launch_bounds__(256)
void MedianFilter2D_68745246540291_kernel(const float* __restrict__ in,
                                          float* __restrict__ out) {
    const int tid   = threadIdx.x;
    const int lane  = tid & 31;
    const int t128  = tid & 127;                 // position within a row-strip
    const int strip = blockIdx.x * 2 + (tid >> 7);

    const int plane = strip >> 5;                // strip / (512/RPT)
    const int sy    = strip & 31;
    const int y0    = sy * RPT;
    const int x0    = t128 * 4;

    const float* __restrict__ ip = in  + (size_t)plane * (IMG_H * IMG_W);
    float*       __restrict__ op = out + (size_t)plane * (IMG_H * IMG_W);

    // rolling window of horizontally-sorted rows
    SortedRow A = load_sort_row(ip, y0 - 1, x0, lane);
    SortedRow B = load_sort_row(ip, y0,     x0, lane);

    #pragma unroll
    for (int i = 0; i < RPT; i++) {
        SortedRow C = load_sort_row(ip, y0 + i + 1, x0, lane);

        float4 res;
        res.x = tail(A.lo0, B.lo0, C.lo0, A.mi0, B.mi0, C.mi0, A.hi0, B.hi0, C.hi0);
        res.y = tail(A.lo1, B.lo1, C.lo1, A.mi1, B.mi1, C.mi1, A.hi1, B.hi1, C.hi1);
        res.z = tail(A.lo2, B.lo2, C.lo2, A.mi2, B.mi2, C.mi2, A.hi2, B.hi2, C.hi2);
        res.w = tail(A.lo3, B.lo3, C.lo3, A.mi3, B.mi3, C.mi3, A.hi3, B.hi3, C.hi3);

        *(float4*)(op + (size_t)(y0 + i) * IMG_W + x0) = res;

        A = B; B = C;   // pure register renaming after full unroll
    }
}

extern "C" void kernel_launch(void* const* d_in, const int* in_sizes, int n_in,
                              void* d_out, int out_size) {
    const float* image = (const float*)d_in[0];
    float* out = (float*)d_out;

    // 48 planes * 32 strips(16 rows) = 1536 strips; 2 strips per 256-thread block
    dim3 block(256, 1, 1);
    dim3 grid(768, 1, 1);
    MedianFilter2D_68745246540291_kernel<<<grid, block>>>(image, out);
}

// round 3
// speedup vs baseline: 2.7133x; 1.2740x over previous
#include <cuda_runtime.h>

#define IMG_W 512
#define IMG_H 512
#define RPT   8       // output rows per thread
#define STRIPS_PER_PLANE (IMG_H / RPT)   // 64

__device__ __forceinline__ float med3f(float a, float b, float c) {
    return fmaxf(fminf(a, b), fminf(fmaxf(a, b), c));
}

__device__ __forceinline__ int reflecty(int y) {
    y = (y < 0) ? -y : y;
    return (y >= IMG_H) ? 2 * IMG_H - 2 - y : y;
}

struct RawRow {
    float4 v;
    float l, r;
};

struct SortedRow {
    float lo0, lo1, lo2, lo3;
    float mi0, mi1, mi2, mi3;
    float hi0, hi1, hi2, hi3;
};

// Three independent loads (no cross-lane dependency): main float4 + 2 halo scalars.
// Halo scalars hit L1 (lines are brought in by neighbor lanes' vector loads).
__device__ __forceinline__ RawRow load_raw(const float* __restrict__ ip,
                                           int y, int x0, int t128) {
    const float* __restrict__ rp = ip + reflecty(y) * IMG_W;
    RawRow o;
    o.v = *(const float4*)(rp + x0);
    const int xl = (t128 == 0)   ? 1         : x0 - 1;   // reflect at image edge
    const int xr = (t128 == 127) ? IMG_W - 2 : x0 + 4;
    o.l = rp[xl];
    o.r = rp[xr];
    return o;
}

__device__ __forceinline__ SortedRow sort_row(const RawRow& rr) {
    float s0 = rr.l, s1 = rr.v.x, s2 = rr.v.y, s3 = rr.v.z, s4 = rr.v.w, s5 = rr.r;
    SortedRow o;
    #define SORT3(a_, b_, c_, LO, MI, HI) {            \
        float a = (a_), b = (b_), c = (c_), t;          \
        t = fminf(a, b); b = fmaxf(a, b); a = t;        \
        t = fminf(b, c); c = fmaxf(b, c); b = t;        \
        t = fminf(a, b); b = fmaxf(a, b); a = t;        \
        o.LO = a; o.MI = b; o.HI = c; }
    SORT3(s0, s1, s2, lo0, mi0, hi0);
    SORT3(s1, s2, s3, lo1, mi1, hi1);
    SORT3(s2, s3, s4, lo2, mi2, hi2);
    SORT3(s3, s4, s5, lo3, mi3, hi3);
    #undef SORT3
    return o;
}

__device__ __forceinline__ float tail(float lA, float lB, float lC,
                                      float mA, float mB, float mC,
                                      float hA, float hB, float hC) {
    float mx = fmaxf(fmaxf(lA, lB), lC);
    float mn = fminf(fminf(hA, hB), hC);
    float md = med3f(mA, mB, mC);
    return med3f(mx, md, mn);
}

__global__ __launch_bounds__(256)
void MedianFilter2D_68745246540291_kernel(const float* __restrict__ in,
                                          float* __restrict__ out) {
    const int tid   = threadIdx.x;
    const int t128  = tid & 127;
    const int strip = blockIdx.x * 2 + (tid >> 7);

    const int plane = strip >> 6;                 // strip / STRIPS_PER_PLANE
    const int sy    = strip & (STRIPS_PER_PLANE - 1);
    const int y0    = sy * RPT;
    const int x0    = t128 * 4;

    const float* __restrict__ ip = in  + (size_t)plane * (IMG_H * IMG_W);
    float*       __restrict__ op = out + (size_t)plane * (IMG_H * IMG_W);

    // Software pipeline: raw row i+1 is loaded one iteration ahead.
    SortedRow A = sort_row(load_raw(ip, y0 - 1, x0, t128));
    SortedRow B = sort_row(load_raw(ip, y0,     x0, t128));
    RawRow nxt  = load_raw(ip, y0 + 1, x0, t128);

    #pragma unroll
    for (int i = 0; i < RPT; i++) {
        RawRow cur = nxt;
        if (i + 1 < RPT)
            nxt = load_raw(ip, y0 + i + 2, x0, t128);   // overlap with compute below

        SortedRow C = sort_row(cur);

        float4 res;
        res.x = tail(A.lo0, B.lo0, C.lo0, A.mi0, B.mi0, C.mi0, A.hi0, B.hi0, C.hi0);
        res.y = tail(A.lo1, B.lo1, C.lo1, A.mi1, B.mi1, C.mi1, A.hi1, B.hi1, C.hi1);
        res.z = tail(A.lo2, B.lo2, C.lo2, A.mi2, B.mi2, C.mi2, A.hi2, B.hi2, C.hi2);
        res.w = tail(A.lo3, B.lo3, C.lo3, A.mi3, B.mi3, C.mi3, A.hi3, B.hi3, C.hi3);

        *(float4*)(op + (size_t)(y0 + i) * IMG_W + x0) = res;

        A = B; B = C;   // register renaming under full unroll
    }
}

extern "C" void kernel_launch(void* const* d_in, const int* in_sizes, int n_in,
                              void* d_out, int out_size) {
    const float* image = (const float*)d_in[0];
    float* out = (float*)d_out;

    // 48 planes * 64 strips(8 rows) = 3072 strips; 2 strips per 256-thread block
    dim3 block(256, 1, 1);
    dim3 grid(48 * STRIPS_PER_PLANE / 2, 1, 1);   // 1536
    MedianFilter2D_68745246540291_kernel<<<grid, block>>>(image, out);
}